// round 3
// baseline (speedup 1.0000x reference)
#include <cuda_runtime.h>

// 2-level 3D inverse db4 DWT.
// Level 1: (16,36,36,36) low + 7×(16,36,36,36) high -> (16,66,66,66)
// Level 0: (16,66,66,66) low + 7×(16,66,66,66) high -> (16,126,126,126)
// Each level = 3 passes (x, then y, then z), each pass merges band pairs:
//   out[i] = sum_d lo[(i>>1)+d]*CLO[i&1][d] + hi[(i>>1)+d]*CHI[i&1][d]
// (derived from conv_transpose(stride=2, padding=L-2); window always in-bounds)

#define BC 16  // batch * channels = 2*8

// db4 reconstruction lowpass g0; g1[k] = (-1)^k * g0[7-k]
// CLO[p][d] = g0[6+p-2d], CHI[p][d] = g1[6+p-2d]
__device__ __constant__ float CLO0[4] = { 0.032883011666982945f, -0.18703481171888114f,  0.6308807679295904f,   0.23037781330885523f };
__device__ __constant__ float CLO1[4] = {-0.010597401784997278f,  0.030841381835986965f, -0.02798376941698385f,  0.7148465705525415f  };
__device__ __constant__ float CHI0[4] = { 0.7148465705525415f,   -0.02798376941698385f,  0.030841381835986965f, -0.010597401784997278f};
__device__ __constant__ float CHI1[4] = {-0.23037781330885523f,  -0.6308807679295904f,   0.18703481171888114f,  -0.032883011666982945f};

// Scratch (sized for level 0, reused by level 1)
__device__ float g_T[4ull * BC * 66 * 66 * 126];   // stage1 out: [4][BC][N][N][2N-6]
__device__ float g_U[2ull * BC * 66 * 126 * 126];  // stage2 out: [2][BC][N][2N-6][2N-6]
__device__ float g_LL[(size_t)BC * 66 * 66 * 66];  // level-1 result

// ---------------- stage 1: synthesis along last (contiguous) axis ----------------
// bands: [low, h0..h6]; pair j merges bands (2j, 2j+1).
// low layout: [BC][N][N][N]; yh layout: [BC][7][N][N][N].
template<int N, bool LOW_FROM_LL>
__global__ __launch_bounds__(256)
void k_stage1(const float* __restrict__ low_in, const float* __restrict__ yh) {
    constexpr int P = N - 3;          // output pairs per row
    constexpr int M = 2 * N - 6;      // output length
    constexpr long long V = (long long)N * N * N;
    constexpr long long TOT = 4LL * BC * N * N * P;

    long long id = (long long)blockIdx.x * blockDim.x + threadIdx.x;
    if (id >= TOT) return;

    int bx = (int)(id % P); long long r = id / P;
    int y  = (int)(r % N); r /= N;
    int z  = (int)(r % N); r /= N;
    int b  = (int)(r % BC);
    int j  = (int)(r / BC);

    const float* low = LOW_FROM_LL ? g_LL : low_in;
    const float* lo = (j == 0) ? (low + (size_t)b * V)
                               : (yh + ((size_t)b * 7 + (2 * j - 1)) * V);
    const float* hi = yh + ((size_t)b * 7 + 2 * j) * V;

    size_t roff = (((size_t)z * N + y) * N) + bx;
    float o0 = 0.f, o1 = 0.f;
#pragma unroll
    for (int d = 0; d < 4; ++d) {
        float l = lo[roff + d];
        float h = hi[roff + d];
        o0 = fmaf(l, CLO0[d], fmaf(h, CHI0[d], o0));
        o1 = fmaf(l, CLO1[d], fmaf(h, CHI1[d], o1));
    }
    float2* dst = (float2*)(g_T + ((((size_t)j * BC + b) * N * N) + (size_t)z * N + y) * M + 2 * bx);
    *dst = make_float2(o0, o1);
}

// ---------------- stage 2: synthesis along middle (y) axis ----------------
// in g_T: [4][BC][Z][NY][X]; out g_U: [2][BC][Z][2*NY-6][X]
template<int Z, int NY, int X>
__global__ __launch_bounds__(256)
void k_stage2() {
    constexpr int P  = NY - 3;
    constexpr int MY = 2 * NY - 6;
    constexpr long long TOT = 2LL * BC * Z * P * X;

    long long id = (long long)blockIdx.x * blockDim.x + threadIdx.x;
    if (id >= TOT) return;

    int x  = (int)(id % X); long long r = id / X;
    int by = (int)(r % P); r /= P;
    int z  = (int)(r % Z); r /= Z;
    int b  = (int)(r % BC);
    int j  = (int)(r / BC);

    const float* lo = g_T + ((((size_t)(2 * j) * BC + b) * Z + z) * NY) * X;
    const float* hi = lo + (size_t)BC * Z * NY * X;

    size_t off = (size_t)by * X + x;
    float o0 = 0.f, o1 = 0.f;
#pragma unroll
    for (int d = 0; d < 4; ++d) {
        float l = lo[off + (size_t)d * X];
        float h = hi[off + (size_t)d * X];
        o0 = fmaf(l, CLO0[d], fmaf(h, CHI0[d], o0));
        o1 = fmaf(l, CLO1[d], fmaf(h, CHI1[d], o1));
    }
    float* dst = g_U + ((((size_t)j * BC + b) * Z + z) * MY + 2 * by) * X + x;
    dst[0] = o0;
    dst[X] = o1;
}

// ---------------- stage 3: synthesis along outer (z) axis ----------------
// in g_U: [2][BC][NZ][PLANE]; out: [BC][2*NZ-6][PLANE]
template<int NZ, int PLANE, bool TO_LL>
__global__ __launch_bounds__(256)
void k_stage3(float* __restrict__ outp) {
    constexpr int P  = NZ - 3;
    constexpr int MZ = 2 * NZ - 6;
    constexpr long long TOT = (long long)BC * P * PLANE;

    long long id = (long long)blockIdx.x * blockDim.x + threadIdx.x;
    if (id >= TOT) return;

    int in = (int)(id % PLANE); long long r = id / PLANE;
    int bz = (int)(r % P);
    int b  = (int)(r / P);

    const float* lo = g_U + (size_t)b * NZ * PLANE;
    const float* hi = g_U + ((size_t)BC + b) * (size_t)NZ * PLANE;

    size_t off = (size_t)bz * PLANE + in;
    float o0 = 0.f, o1 = 0.f;
#pragma unroll
    for (int d = 0; d < 4; ++d) {
        float l = lo[off + (size_t)d * PLANE];
        float h = hi[off + (size_t)d * PLANE];
        o0 = fmaf(l, CLO0[d], fmaf(h, CHI0[d], o0));
        o1 = fmaf(l, CLO1[d], fmaf(h, CHI1[d], o1));
    }
    float* out = TO_LL ? g_LL : outp;
    float* dst = out + ((size_t)b * MZ + 2 * bz) * PLANE + in;
    dst[0]     = o0;
    dst[PLANE] = o1;
}

static inline unsigned gblocks(long long total, int tb) {
    return (unsigned)((total + tb - 1) / tb);
}

extern "C" void kernel_launch(void* const* d_in, const int* in_sizes, int n_in,
                              void* d_out, int out_size) {
    // Identify inputs by element count (robust to metadata ordering).
    const float *yl = nullptr, *yh0 = nullptr, *yh1 = nullptr;
    for (int i = 0; i < n_in; ++i) {
        if      (in_sizes[i] == 746496)   yl  = (const float*)d_in[i];  // (2,8,36,36,36)
        else if (in_sizes[i] == 32199552) yh0 = (const float*)d_in[i];  // (2,8,7,66,66,66)
        else if (in_sizes[i] == 5225472)  yh1 = (const float*)d_in[i];  // (2,8,7,36,36,36)
    }
    float* out = (float*)d_out;
    const int TB = 256;

    // ---- Level 1: 36 -> 66 ----
    k_stage1<36, false><<<gblocks(4LL * BC * 36 * 36 * 33, TB), TB>>>(yl, yh1);
    k_stage2<36, 36, 66><<<gblocks(2LL * BC * 36 * 33 * 66, TB), TB>>>();
    k_stage3<36, 66 * 66, true><<<gblocks((long long)BC * 33 * 66 * 66, TB), TB>>>(nullptr);

    // ---- Level 0: 66 -> 126 ----
    k_stage1<66, true><<<gblocks(4LL * BC * 66 * 66 * 63, TB), TB>>>(nullptr, yh0);
    k_stage2<66, 66, 126><<<gblocks(2LL * BC * 66 * 63 * 126, TB), TB>>>();
    k_stage3<66, 126 * 126, false><<<gblocks((long long)BC * 63 * 126 * 126, TB), TB>>>(out);
}